// round 2
// baseline (speedup 1.0000x reference)
#include <cuda_runtime.h>

#define N_NODES 32
#define DIM 96
#define N_EDGES 256
#define PPAIR 1024
#define M_TOT (PPAIR * N_EDGES)   // 262144 samples

// ---------------- scratch (static device globals; no allocation) ----------------
__device__ float g_feat[M_TOT * 16];     // 16 MB: conv features per sample
__device__ float g_predsT[M_TOT];        // preds transposed: [e * 1024 + p]
__device__ float g_rbc[N_NODES];

// =======================================================================
// Kernel 1: conv stack. One thread per sample. Receptive-field chunked:
// each of the 4 final pooled positions m needs h1 cols [4m,4m+10),
// h2 cols [2m,2m+4) -> only ~56 live floats at a time.
// =======================================================================
__global__ void __launch_bounds__(256) conv_kernel(
    const float* __restrict__ emb, const int* __restrict__ edges,
    const float* __restrict__ w1, const float* __restrict__ b1,
    const float* __restrict__ w2, const float* __restrict__ b2,
    const float* __restrict__ w3, const float* __restrict__ b3)
{
    __shared__ float semb[N_NODES * DIM];
    __shared__ int   sedge[N_EDGES * 2];
    __shared__ float sw1[48], sb1[4], sw2[48], sb2[4], sw3[48], sb3[4];
    __shared__ float sfeat[256][17];   // padded to avoid bank conflicts

    int tid = threadIdx.x;
    for (int i = tid; i < N_NODES * DIM; i += 256) semb[i] = emb[i];
    for (int i = tid; i < N_EDGES * 2; i += 256) sedge[i] = edges[i];
    if (tid < 48) { sw1[tid] = w1[tid]; sw2[tid] = w2[tid]; sw3[tid] = w3[tid]; }
    if (tid < 4)  { sb1[tid] = b1[tid]; sb2[tid] = b2[tid]; sb3[tid] = b3[tid]; }
    __syncthreads();

    int gidx = blockIdx.x * 256 + tid;
    int p = gidx >> 8, e = gidx & 255;
    int s = p >> 5, t = p & 31;
    int xb[4];
    xb[0] = s * DIM;
    xb[1] = t * DIM;
    xb[2] = sedge[2 * e] * DIM;
    xb[3] = sedge[2 * e + 1] * DIM;

#pragma unroll
    for (int m = 0; m < 4; m++) {
        float h1c[4][10];
#pragma unroll
        for (int c = 0; c < 10; c++) {
            int pos0 = (4 * m + c) * 4;           // conv1 stride-2 + pool2 => x pos 4*C
            float xv[4][5];
#pragma unroll
            for (int i = 0; i < 4; i++)
#pragma unroll
                for (int pp = 0; pp < 5; pp++)
                    xv[i][pp] = semb[xb[i] + pos0 + pp];
#pragma unroll
            for (int o = 0; o < 4; o++) {
                float y0 = sb1[o], y1 = sb1[o];
#pragma unroll
                for (int i = 0; i < 4; i++)
#pragma unroll
                    for (int k = 0; k < 3; k++) {
                        float w = sw1[o * 12 + i * 3 + k];
                        y0 += w * xv[i][k];
                        y1 += w * xv[i][k + 2];
                    }
                h1c[o][c] = fmaxf(fmaxf(y0, y1), 0.f);   // pool(relu) = relu(max)
            }
        }
        float h2c[4][4];
#pragma unroll
        for (int c = 0; c < 4; c++) {
#pragma unroll
            for (int o = 0; o < 4; o++) {
                float y0 = sb2[o], y1 = sb2[o];
#pragma unroll
                for (int i = 0; i < 4; i++)
#pragma unroll
                    for (int k = 0; k < 3; k++) {
                        float w = sw2[o * 12 + i * 3 + k];
                        y0 += w * h1c[i][2 * c + k];
                        y1 += w * h1c[i][2 * c + 1 + k];
                    }
                h2c[o][c] = fmaxf(fmaxf(y0, y1), 0.f);
            }
        }
#pragma unroll
        for (int o = 0; o < 4; o++) {
            float y0 = sb3[o], y1 = sb3[o];
#pragma unroll
            for (int i = 0; i < 4; i++)
#pragma unroll
                for (int k = 0; k < 3; k++) {
                    float w = sw3[o * 12 + i * 3 + k];
                    y0 += w * h2c[i][k];
                    y1 += w * h2c[i][k + 1];
                }
            sfeat[tid][o * 4 + m] = fmaxf(fmaxf(y0, y1), 0.f);  // flatten: c*4+l
        }
    }
    __syncthreads();
#pragma unroll
    for (int ii = 0; ii < 16; ii++) {
        int l = tid + ii * 256;           // coalesced store of 256x16 tile
        g_feat[blockIdx.x * 4096 + l] = sfeat[l >> 4][l & 15];
    }
}

// =======================================================================
// Kernel 2: fused FC stack (the hot kernel). 256 threads, 64 samples/block.
// fc1 -> smem H1[k][m]; loop over 4 N2-tiles of 64: fc2 -> smem H2[j][m],
// fc3 accumulated into 4x8 register tile; fc4 via shfl reduce.
// =======================================================================
#define MT 64
#define FC_SMEM_FLOATS (1024 + 128*68 + 128*64 + 64*68 + 64*128)
#define FC_SMEM_BYTES (FC_SMEM_FLOATS * 4)

__global__ void __launch_bounds__(256) fc_kernel(
    const float* __restrict__ fc1w, const float* __restrict__ fc1b,
    const float* __restrict__ fc2w, const float* __restrict__ fc2b,
    const float* __restrict__ fc3w, const float* __restrict__ fc3b,
    const float* __restrict__ fc4w, const float* __restrict__ fc4b)
{
    extern __shared__ float sm[];
    float* sF  = sm;                 // [64][16]
    float* sH1 = sF + 1024;          // [128][68]  (transposed: [k][m], pad 4)
    float* sW2 = sH1 + 128 * 68;     // [128][64]
    float* sH2 = sW2 + 128 * 64;     // [64][68]   (transposed: [j][m], pad 4)
    float* sW3 = sH2 + 64 * 68;      // [64][128]

    int tid = threadIdx.x;
    int m0 = blockIdx.x * MT;

#pragma unroll
    for (int i = 0; i < 4; i++)
        sF[tid + i * 256] = g_feat[m0 * 16 + tid + i * 256];
    __syncthreads();

    // ---- fc1: h1[64][128] = relu(F @ W1 + b1), stored transposed ----
    {
        int nn = tid & 127, half = tid >> 7;
        float w1r[16];
#pragma unroll
        for (int k = 0; k < 16; k++) w1r[k] = fc1w[k * 128 + nn];
        float bb = fc1b[nn];
#pragma unroll 4
        for (int mm = 0; mm < 32; mm++) {
            int m = half * 32 + mm;
            float acc = bb;
#pragma unroll
            for (int k = 0; k < 16; k++) acc += sF[m * 16 + k] * w1r[k];
            sH1[nn * 68 + m] = fmaxf(acc, 0.f);
        }
    }

    int mi = tid >> 4, ni = tid & 15;    // mi: 4 samples, ni: output group
    float acc3[4][8];
#pragma unroll
    for (int ii = 0; ii < 4; ii++)
#pragma unroll
        for (int oo = 0; oo < 8; oo++) acc3[ii][oo] = 0.f;

    const float4* fc2wv = reinterpret_cast<const float4*>(fc2w);
    const float4* fc3wv = reinterpret_cast<const float4*>(fc3w);
    float4* sW2v = reinterpret_cast<float4*>(sW2);
    float4* sW3v = reinterpret_cast<float4*>(sW3);
    const float4* H1v = reinterpret_cast<const float4*>(sH1);
    const float4* H2v = reinterpret_cast<const float4*>(sH2);

    for (int nt = 0; nt < 4; nt++) {
        int ntb = nt * 64;
        __syncthreads();  // fc1 done (iter 0) / prior fc3 reads done before overwrite
#pragma unroll
        for (int i = 0; i < 8; i++) {    // load W2 tile 128x64
            int idx = tid + i * 256;
            int k = idx >> 4, c4 = idx & 15;
            sW2v[k * 16 + c4] = fc2wv[k * 64 + (ntb >> 2) + c4];
        }
#pragma unroll
        for (int i = 0; i < 8; i++) {    // load W3 tile 64x128
            int idx = tid + i * 256;
            int j = idx >> 5, c4 = idx & 31;
            sW3v[j * 32 + c4] = fc3wv[(ntb + j) * 32 + c4];
        }
        __syncthreads();

        // ---- fc2: h2tile[64][64] = relu(H1 @ W2tile + b2) ----
        float a2[4][4];
#pragma unroll
        for (int ii = 0; ii < 4; ii++)
#pragma unroll
            for (int jj = 0; jj < 4; jj++) a2[ii][jj] = 0.f;
#pragma unroll 4
        for (int k = 0; k < 128; k++) {
            float4 a = H1v[k * 17 + mi];
            float4 b = sW2v[k * 16 + ni];
            a2[0][0] += a.x * b.x; a2[0][1] += a.x * b.y; a2[0][2] += a.x * b.z; a2[0][3] += a.x * b.w;
            a2[1][0] += a.y * b.x; a2[1][1] += a.y * b.y; a2[1][2] += a.y * b.z; a2[1][3] += a.y * b.w;
            a2[2][0] += a.z * b.x; a2[2][1] += a.z * b.y; a2[2][2] += a.z * b.z; a2[2][3] += a.z * b.w;
            a2[3][0] += a.w * b.x; a2[3][1] += a.w * b.y; a2[3][2] += a.w * b.z; a2[3][3] += a.w * b.w;
        }
#pragma unroll
        for (int jj = 0; jj < 4; jj++) {
            float bb = fc2b[ntb + 4 * ni + jj];
#pragma unroll
            for (int ii = 0; ii < 4; ii++)
                sH2[(4 * ni + jj) * 68 + 4 * mi + ii] = fmaxf(a2[ii][jj] + bb, 0.f);
        }
        __syncthreads();

        // ---- fc3 accumulate: h3[64][128] += H2tile @ W3tile ----
#pragma unroll 4
        for (int j = 0; j < 64; j++) {
            float4 a  = H2v[j * 17 + mi];
            float4 b0 = sW3v[j * 32 + 2 * ni];
            float4 b1 = sW3v[j * 32 + 2 * ni + 1];
            acc3[0][0] += a.x * b0.x; acc3[0][1] += a.x * b0.y; acc3[0][2] += a.x * b0.z; acc3[0][3] += a.x * b0.w;
            acc3[0][4] += a.x * b1.x; acc3[0][5] += a.x * b1.y; acc3[0][6] += a.x * b1.z; acc3[0][7] += a.x * b1.w;
            acc3[1][0] += a.y * b0.x; acc3[1][1] += a.y * b0.y; acc3[1][2] += a.y * b0.z; acc3[1][3] += a.y * b0.w;
            acc3[1][4] += a.y * b1.x; acc3[1][5] += a.y * b1.y; acc3[1][6] += a.y * b1.z; acc3[1][7] += a.y * b1.w;
            acc3[2][0] += a.z * b0.x; acc3[2][1] += a.z * b0.y; acc3[2][2] += a.z * b0.z; acc3[2][3] += a.z * b0.w;
            acc3[2][4] += a.z * b1.x; acc3[2][5] += a.z * b1.y; acc3[2][6] += a.z * b1.z; acc3[2][7] += a.z * b1.w;
            acc3[3][0] += a.w * b0.x; acc3[3][1] += a.w * b0.y; acc3[3][2] += a.w * b0.z; acc3[3][3] += a.w * b0.w;
            acc3[3][4] += a.w * b1.x; acc3[3][5] += a.w * b1.y; acc3[3][6] += a.w * b1.z; acc3[3][7] += a.w * b1.w;
        }
    }

    // ---- fc4: pred = relu(h3 + b3) @ w4 + b4, reduce over the 16 ni lanes ----
    float b3r[8], w4r[8];
#pragma unroll
    for (int oo = 0; oo < 8; oo++) {
        b3r[oo] = fc3b[8 * ni + oo];
        w4r[oo] = fc4w[8 * ni + oo];
    }
    float bias4 = fc4b[0];
#pragma unroll
    for (int ii = 0; ii < 4; ii++) {
        float part = 0.f;
#pragma unroll
        for (int oo = 0; oo < 8; oo++)
            part += fmaxf(acc3[ii][oo] + b3r[oo], 0.f) * w4r[oo];
        part += __shfl_xor_sync(0xffffffffu, part, 8);
        part += __shfl_xor_sync(0xffffffffu, part, 4);
        part += __shfl_xor_sync(0xffffffffu, part, 2);
        part += __shfl_xor_sync(0xffffffffu, part, 1);
        if (ni == 0) {
            int gidx = m0 + 4 * mi + ii;
            int p = gidx >> 8, e = gidx & 255;
            float pred = part + bias4;
            if ((p >> 5) == (p & 31)) pred = 0.f;   // s == t mask
            g_predsT[e * 1024 + p] = pred;          // transposed for prop coalescing
        }
    }
}

// =======================================================================
// Kernel 3: propagation, fully fused (rows independent). 1 thread = 1 row p.
// x row lives in a stride-33 smem slice (conflict-free for uniform index).
// =======================================================================
__global__ void __launch_bounds__(128) prop_kernel(const int* __restrict__ edges)
{
    __shared__ int su[N_EDGES], sv[N_EDGES];
    __shared__ float sx[2][128 * 33];
    __shared__ float srbc[N_NODES];

    int tid = threadIdx.x;
    if (tid < 32) srbc[tid] = 0.f;
    for (int i = tid; i < N_EDGES; i += 128) { su[i] = edges[2 * i]; sv[i] = edges[2 * i + 1]; }
    __syncthreads();

    int p = blockIdx.x * 128 + tid;
    int s = p >> 5, t = p & 31;

    float racc[32];
#pragma unroll
    for (int j = 0; j < 32; j++) racc[j] = 0.f;

    float* x0 = &sx[0][tid * 33];
    float* x1 = &sx[1][tid * 33];
#pragma unroll
    for (int j = 0; j < 32; j++) x0[j] = (j == s) ? 1.f : 0.f;

    if (s != t) {
        for (int step = 0; step < 3; step++) {
            float* xc = (step & 1) ? x1 : x0;
            float* xn = (step & 1) ? x0 : x1;
#pragma unroll
            for (int j = 0; j < 32; j++) xn[j] = 0.f;
#pragma unroll 4
            for (int e = 0; e < N_EDGES; e++) {
                float pr = g_predsT[e * 1024 + p];      // coalesced
                xn[sv[e]] += xc[su[e]] * pr;
            }
#pragma unroll
            for (int j = 0; j < 32; j++) racc[j] += xn[j];
        }
    }
#pragma unroll
    for (int j = 0; j < 32; j++) atomicAdd(&srbc[j], racc[j]);
    __syncthreads();
    if (tid < 32) atomicAdd(&g_rbc[tid], srbc[tid]);
}

__global__ void zero_rbc_kernel() {
    if (threadIdx.x < N_NODES) g_rbc[threadIdx.x] = 0.f;
}

__global__ void norm_kernel(float* __restrict__ out) {
    int l = threadIdx.x;
    float v = g_rbc[l];
    float sum = v;
#pragma unroll
    for (int o = 16; o > 0; o >>= 1) sum += __shfl_xor_sync(0xffffffffu, sum, o);
    out[l] = v / sum;
}

// =======================================================================
extern "C" void kernel_launch(void* const* d_in, const int* in_sizes, int n_in,
                              void* d_out, int out_size)
{
    const float* emb  = (const float*)d_in[0];
    const int*   edges= (const int*)  d_in[1];
    const float* w1   = (const float*)d_in[2];
    const float* b1   = (const float*)d_in[3];
    const float* w2   = (const float*)d_in[4];
    const float* b2   = (const float*)d_in[5];
    const float* w3   = (const float*)d_in[6];
    const float* b3   = (const float*)d_in[7];
    const float* fc1w = (const float*)d_in[8];
    const float* fc1b = (const float*)d_in[9];
    const float* fc2w = (const float*)d_in[10];
    const float* fc2b = (const float*)d_in[11];
    const float* fc3w = (const float*)d_in[12];
    const float* fc3b = (const float*)d_in[13];
    const float* fc4w = (const float*)d_in[14];
    const float* fc4b = (const float*)d_in[15];
    float* out = (float*)d_out;

    cudaFuncSetAttribute(fc_kernel, cudaFuncAttributeMaxDynamicSharedMemorySize,
                         FC_SMEM_BYTES);

    conv_kernel<<<M_TOT / 256, 256>>>(emb, edges, w1, b1, w2, b2, w3, b3);
    fc_kernel<<<M_TOT / MT, 256, FC_SMEM_BYTES>>>(fc1w, fc1b, fc2w, fc2b,
                                                  fc3w, fc3b, fc4w, fc4b);
    zero_rbc_kernel<<<1, 32>>>();
    prop_kernel<<<PPAIR / 128, 128>>>(edges);
    norm_kernel<<<1, 32>>>(out);
}

// round 3
// speedup vs baseline: 1.0411x; 1.0411x over previous
#include <cuda_runtime.h>
#include <cstdint>

#define N_NODES 32
#define DIM 96
#define N_EDGES 256
#define PPAIR 1024
#define M_TOT (PPAIR * N_EDGES)   // 262144 samples

// ---------------- scratch (static device globals; no allocation) ----------------
__device__ float g_feat[M_TOT * 16];     // conv features per sample
__device__ float g_preds[M_TOT];         // preds row-major: [p * 256 + e]
__device__ float g_rbc[N_NODES];

// ---------------- f32x2 helpers (sm_103a packed fp32 FMA) ----------------
__device__ __forceinline__ void fma2(unsigned long long& d,
                                     unsigned long long a,
                                     unsigned long long b) {
    asm("fma.rn.f32x2 %0, %1, %2, %3;" : "=l"(d) : "l"(a), "l"(b), "l"(d));
}
__device__ __forceinline__ unsigned long long pack2(float x) {
    unsigned long long r;
    asm("mov.b64 %0, {%1, %1};" : "=l"(r) : "f"(x));
    return r;
}
__device__ __forceinline__ float2 unpack2(unsigned long long v) {
    float2 f;
    asm("mov.b64 {%0, %1}, %2;" : "=f"(f.x), "=f"(f.y) : "l"(v));
    return f;
}
__device__ __forceinline__ void lds_v2u64(unsigned long long& a,
                                          unsigned long long& b, uint32_t addr) {
    asm volatile("ld.shared.v2.u64 {%0, %1}, [%2];"
                 : "=l"(a), "=l"(b) : "r"(addr));
}

// =======================================================================
// Kernel 1: conv stack. One thread per sample, receptive-field chunked.
// =======================================================================
__global__ void __launch_bounds__(256) conv_kernel(
    const float* __restrict__ emb, const int* __restrict__ edges,
    const float* __restrict__ w1, const float* __restrict__ b1,
    const float* __restrict__ w2, const float* __restrict__ b2,
    const float* __restrict__ w3, const float* __restrict__ b3)
{
    __shared__ float semb[N_NODES * DIM];
    __shared__ int   sedge[N_EDGES * 2];
    __shared__ float sw1[48], sb1[4], sw2[48], sb2[4], sw3[48], sb3[4];
    __shared__ float sfeat[256][17];

    int tid = threadIdx.x;
    for (int i = tid; i < N_NODES * DIM; i += 256) semb[i] = emb[i];
    for (int i = tid; i < N_EDGES * 2; i += 256) sedge[i] = edges[i];
    if (tid < 48) { sw1[tid] = w1[tid]; sw2[tid] = w2[tid]; sw3[tid] = w3[tid]; }
    if (tid < 4)  { sb1[tid] = b1[tid]; sb2[tid] = b2[tid]; sb3[tid] = b3[tid]; }
    __syncthreads();

    int gidx = blockIdx.x * 256 + tid;
    int p = gidx >> 8, e = gidx & 255;
    int s = p >> 5, t = p & 31;
    int xb[4];
    xb[0] = s * DIM;
    xb[1] = t * DIM;
    xb[2] = sedge[2 * e] * DIM;
    xb[3] = sedge[2 * e + 1] * DIM;

#pragma unroll
    for (int m = 0; m < 4; m++) {
        float h1c[4][10];
#pragma unroll
        for (int c = 0; c < 10; c++) {
            int pos0 = (4 * m + c) * 4;
            float xv[4][5];
#pragma unroll
            for (int i = 0; i < 4; i++)
#pragma unroll
                for (int pp = 0; pp < 5; pp++)
                    xv[i][pp] = semb[xb[i] + pos0 + pp];
#pragma unroll
            for (int o = 0; o < 4; o++) {
                float y0 = sb1[o], y1 = sb1[o];
#pragma unroll
                for (int i = 0; i < 4; i++)
#pragma unroll
                    for (int k = 0; k < 3; k++) {
                        float w = sw1[o * 12 + i * 3 + k];
                        y0 += w * xv[i][k];
                        y1 += w * xv[i][k + 2];
                    }
                h1c[o][c] = fmaxf(fmaxf(y0, y1), 0.f);
            }
        }
        float h2c[4][4];
#pragma unroll
        for (int c = 0; c < 4; c++) {
#pragma unroll
            for (int o = 0; o < 4; o++) {
                float y0 = sb2[o], y1 = sb2[o];
#pragma unroll
                for (int i = 0; i < 4; i++)
#pragma unroll
                    for (int k = 0; k < 3; k++) {
                        float w = sw2[o * 12 + i * 3 + k];
                        y0 += w * h1c[i][2 * c + k];
                        y1 += w * h1c[i][2 * c + 1 + k];
                    }
                h2c[o][c] = fmaxf(fmaxf(y0, y1), 0.f);
            }
        }
#pragma unroll
        for (int o = 0; o < 4; o++) {
            float y0 = sb3[o], y1 = sb3[o];
#pragma unroll
            for (int i = 0; i < 4; i++)
#pragma unroll
                for (int k = 0; k < 3; k++) {
                    float w = sw3[o * 12 + i * 3 + k];
                    y0 += w * h2c[i][k];
                    y1 += w * h2c[i][k + 1];
                }
            sfeat[tid][o * 4 + m] = fmaxf(fmaxf(y0, y1), 0.f);
        }
    }
    __syncthreads();
#pragma unroll
    for (int ii = 0; ii < 16; ii++) {
        int l = tid + ii * 256;
        g_feat[blockIdx.x * 4096 + l] = sfeat[l >> 4][l & 15];
    }
}

// =======================================================================
// Kernel 2: fused FC stack with fma.rn.f32x2 (packed fp32, 2 FMA/instr).
// 256 threads, 64 samples/block. Thread tile: 2m x 8n (fc2), 2m x 16n (fc3).
// W2/W3 in 8 per-lane smem panels (stride 1028 floats) -> conflict-free
// ld.shared.v2.u64 delivers pre-packed f32x2 operands (no per-B movs).
// =======================================================================
#define MT 64
// smem layout in floats:
#define SF_OFF   0                       // [64][16]            = 1024
#define SH1_OFF  1024                    // [128][68]           = 8704
#define SW2_OFF  (SH1_OFF + 8704)        // 8 panels x 1028     = 8224
#define SH2_OFF  (SW2_OFF + 8224)        // [64][68]            = 4352
#define SW3_OFF  (SH2_OFF + 4352)        // 8 panels x 1028     = 8224
#define FC_SMEM_FLOATS (SW3_OFF + 8224)  // 30528
#define FC_SMEM_BYTES (FC_SMEM_FLOATS * 4)

__global__ void __launch_bounds__(256) fc_kernel(
    const float* __restrict__ fc1w, const float* __restrict__ fc1b,
    const float* __restrict__ fc2w, const float* __restrict__ fc2b,
    const float* __restrict__ fc3w, const float* __restrict__ fc3b,
    const float* __restrict__ fc4w, const float* __restrict__ fc4b)
{
    extern __shared__ float sm[];
    float* sF  = sm + SF_OFF;
    float* sH1 = sm + SH1_OFF;
    float* sH2 = sm + SH2_OFF;
    uint32_t smem_u32 = (uint32_t)__cvta_generic_to_shared(sm);

    int tid = threadIdx.x;
    int m0 = blockIdx.x * MT;

#pragma unroll
    for (int i = 0; i < 4; i++)
        sF[tid + i * 256] = g_feat[m0 * 16 + tid + i * 256];
    __syncthreads();

    // ---- fc1: h1[64][128] = relu(F @ W1 + b1), stored transposed [k][m] ----
    {
        int nn = tid & 127, half = tid >> 7;
        float w1r[16];
#pragma unroll
        for (int k = 0; k < 16; k++) w1r[k] = fc1w[k * 128 + nn];
        float bb = fc1b[nn];
#pragma unroll 4
        for (int mm = 0; mm < 32; mm++) {
            int m = half * 32 + mm;
            float acc = bb;
#pragma unroll
            for (int k = 0; k < 16; k++) acc += sF[m * 16 + k] * w1r[k];
            sH1[nn * 68 + m] = fmaxf(acc, 0.f);
        }
    }

    int ni = tid & 7, mi = tid >> 3;    // mi: 2 samples (2*mi, 2*mi+1)
    const float2* H1m = (const float2*)sH1;   // stride 34 float2
    const float2* H2m = (const float2*)sH2;
    const float4* fc2wv = (const float4*)fc2w;
    const float4* fc3wv = (const float4*)fc3w;
    uint32_t w2a = smem_u32 + (SW2_OFF + ni * 1028) * 4;
    uint32_t w3a = smem_u32 + (SW3_OFF + ni * 1028) * 4;

    unsigned long long acc3[16];
#pragma unroll
    for (int q = 0; q < 16; q++) acc3[q] = 0ull;

    for (int nt = 0; nt < 4; nt++) {
        int ntb = nt * 64;
        __syncthreads();  // prior fc3 reads done before W tiles are overwritten
        // ---- load W2 tile 128x64 into 8 panels (panel = n-group of 8) ----
#pragma unroll
        for (int i = 0; i < 8; i++) {
            int idx = tid + i * 256;
            int k = idx >> 4, c4 = idx & 15;
            int off = SW2_OFF + (c4 >> 1) * 1028 + k * 8 + (c4 & 1) * 4;
            *(float4*)(sm + off) = fc2wv[k * 64 + nt * 16 + c4];
        }
        // ---- load W3 tile 64x128 into 8 panels (panel = n-group of 16) ----
#pragma unroll
        for (int i = 0; i < 8; i++) {
            int idx = tid + i * 256;
            int j = idx >> 5, c4 = idx & 31;
            int off = SW3_OFF + (c4 >> 2) * 1028 + j * 16 + (c4 & 3) * 4;
            *(float4*)(sm + off) = fc3wv[(ntb + j) * 32 + c4];
        }
        __syncthreads();

        // ---- fc2: h2tile[64][64] = relu(H1 @ W2tile + b2), tile 2m x 8n ----
        unsigned long long a2[8];
#pragma unroll
        for (int q = 0; q < 8; q++) a2[q] = 0ull;
#pragma unroll 4
        for (int k = 0; k < 128; k++) {
            float2 a = H1m[k * 34 + mi];
            unsigned long long pa0 = pack2(a.x), pa1 = pack2(a.y);
            unsigned long long b0, b1, b2, b3;
            lds_v2u64(b0, b1, w2a + k * 32);
            lds_v2u64(b2, b3, w2a + k * 32 + 16);
            fma2(a2[0], pa0, b0); fma2(a2[1], pa0, b1);
            fma2(a2[2], pa0, b2); fma2(a2[3], pa0, b3);
            fma2(a2[4], pa1, b0); fma2(a2[5], pa1, b1);
            fma2(a2[6], pa1, b2); fma2(a2[7], pa1, b3);
        }
#pragma unroll
        for (int c = 0; c < 4; c++) {
            int n0 = 8 * ni + 2 * c;
            float bbx = fc2b[ntb + n0], bby = fc2b[ntb + n0 + 1];
            float2 h0 = unpack2(a2[c]);      // m = 2*mi
            float2 h1_ = unpack2(a2[4 + c]); // m = 2*mi + 1
            sH2[n0 * 68 + 2 * mi]           = fmaxf(h0.x + bbx, 0.f);
            sH2[(n0 + 1) * 68 + 2 * mi]     = fmaxf(h0.y + bby, 0.f);
            sH2[n0 * 68 + 2 * mi + 1]       = fmaxf(h1_.x + bbx, 0.f);
            sH2[(n0 + 1) * 68 + 2 * mi + 1] = fmaxf(h1_.y + bby, 0.f);
        }
        __syncthreads();

        // ---- fc3 accumulate: h3[64][128] += H2tile @ W3tile, tile 2m x 16n ----
#pragma unroll 4
        for (int j = 0; j < 64; j++) {
            float2 a = H2m[j * 34 + mi];
            unsigned long long pa0 = pack2(a.x), pa1 = pack2(a.y);
            unsigned long long c0, c1, c2, c3, c4, c5, c6, c7;
            lds_v2u64(c0, c1, w3a + j * 64);
            lds_v2u64(c2, c3, w3a + j * 64 + 16);
            lds_v2u64(c4, c5, w3a + j * 64 + 32);
            lds_v2u64(c6, c7, w3a + j * 64 + 48);
            fma2(acc3[0], pa0, c0); fma2(acc3[1], pa0, c1);
            fma2(acc3[2], pa0, c2); fma2(acc3[3], pa0, c3);
            fma2(acc3[4], pa0, c4); fma2(acc3[5], pa0, c5);
            fma2(acc3[6], pa0, c6); fma2(acc3[7], pa0, c7);
            fma2(acc3[8], pa1, c0); fma2(acc3[9], pa1, c1);
            fma2(acc3[10], pa1, c2); fma2(acc3[11], pa1, c3);
            fma2(acc3[12], pa1, c4); fma2(acc3[13], pa1, c5);
            fma2(acc3[14], pa1, c6); fma2(acc3[15], pa1, c7);
        }
    }

    // ---- fc4: pred = relu(h3 + b3) @ w4 + b4, reduce over 8 ni lanes ----
    float part0 = 0.f, part1 = 0.f;
#pragma unroll
    for (int q = 0; q < 8; q++) {
        int n0 = 16 * ni + 2 * q;
        float b3a = fc3b[n0], b3b = fc3b[n0 + 1];
        float w4a = fc4w[n0], w4b = fc4w[n0 + 1];
        float2 h0 = unpack2(acc3[q]);
        float2 h1_ = unpack2(acc3[8 + q]);
        part0 += fmaxf(h0.x + b3a, 0.f) * w4a + fmaxf(h0.y + b3b, 0.f) * w4b;
        part1 += fmaxf(h1_.x + b3a, 0.f) * w4a + fmaxf(h1_.y + b3b, 0.f) * w4b;
    }
#pragma unroll
    for (int o = 4; o > 0; o >>= 1) {
        part0 += __shfl_xor_sync(0xffffffffu, part0, o);
        part1 += __shfl_xor_sync(0xffffffffu, part1, o);
    }
    if (ni == 0) {
        float bias4 = fc4b[0];
#pragma unroll
        for (int mm = 0; mm < 2; mm++) {
            int gidx = m0 + 2 * mi + mm;
            int p = gidx >> 8;
            float pred = (mm == 0 ? part0 : part1) + bias4;
            if ((p >> 5) == (p & 31)) pred = 0.f;   // s == t mask
            g_preds[gidx] = pred;                   // row-major [p][e]
        }
    }
}

// =======================================================================
// Kernel 3: propagation — warp per row p, 8 edges per lane, lane-private
// stride-33 partial slices (conflict-free), x state lane-resident via shfl.
// =======================================================================
#define PW 8
__global__ void __launch_bounds__(PW * 32) prop_kernel(const int* __restrict__ edges)
{
    __shared__ float spart[PW][32 * 33];
    __shared__ float srbc[N_NODES];
    __shared__ int sue[N_EDGES], sve[N_EDGES];

    int tid = threadIdx.x, l = tid & 31, w = tid >> 5;
    if (tid < 32) srbc[tid] = 0.f;
    for (int i = tid; i < N_EDGES; i += PW * 32) {
        sue[i] = edges[2 * i];
        sve[i] = edges[2 * i + 1];
    }
    __syncthreads();

    int p = blockIdx.x * PW + w;
    int s = p >> 5;

    int eu[8], ev[8];
    float pr[8];
#pragma unroll
    for (int k = 0; k < 8; k++) { eu[k] = sue[l * 8 + k]; ev[k] = sve[l * 8 + k]; }
    {
        float4 p0 = *(const float4*)&g_preds[p * 256 + l * 8];
        float4 p1 = *(const float4*)&g_preds[p * 256 + l * 8 + 4];
        pr[0] = p0.x; pr[1] = p0.y; pr[2] = p0.z; pr[3] = p0.w;
        pr[4] = p1.x; pr[5] = p1.y; pr[6] = p1.z; pr[7] = p1.w;
    }

    float x = (l == s) ? 1.f : 0.f;
    float racc = 0.f;
    float* part = spart[w];

    for (int step = 0; step < 3; step++) {
#pragma unroll
        for (int j = 0; j < 32; j++) part[l * 33 + j] = 0.f;
        __syncwarp();
#pragma unroll
        for (int k = 0; k < 8; k++) {
            float xv = __shfl_sync(0xffffffffu, x, eu[k]);
            part[l * 33 + ev[k]] += xv * pr[k];
        }
        __syncwarp();
        float xn = 0.f;
#pragma unroll
        for (int i = 0; i < 32; i++) xn += part[i * 33 + l];
        x = xn;
        racc += xn;
        __syncwarp();
    }

    atomicAdd(&srbc[l], racc);
    __syncthreads();
    if (tid < 32) atomicAdd(&g_rbc[tid], srbc[tid]);
}

__global__ void zero_rbc_kernel() {
    if (threadIdx.x < N_NODES) g_rbc[threadIdx.x] = 0.f;
}

__global__ void norm_kernel(float* __restrict__ out) {
    int l = threadIdx.x;
    float v = g_rbc[l];
    float sum = v;
#pragma unroll
    for (int o = 16; o > 0; o >>= 1) sum += __shfl_xor_sync(0xffffffffu, sum, o);
    out[l] = v / sum;
}

// =======================================================================
extern "C" void kernel_launch(void* const* d_in, const int* in_sizes, int n_in,
                              void* d_out, int out_size)
{
    const float* emb  = (const float*)d_in[0];
    const int*   edges= (const int*)  d_in[1];
    const float* w1   = (const float*)d_in[2];
    const float* b1   = (const float*)d_in[3];
    const float* w2   = (const float*)d_in[4];
    const float* b2   = (const float*)d_in[5];
    const float* w3   = (const float*)d_in[6];
    const float* b3   = (const float*)d_in[7];
    const float* fc1w = (const float*)d_in[8];
    const float* fc1b = (const float*)d_in[9];
    const float* fc2w = (const float*)d_in[10];
    const float* fc2b = (const float*)d_in[11];
    const float* fc3w = (const float*)d_in[12];
    const float* fc3b = (const float*)d_in[13];
    const float* fc4w = (const float*)d_in[14];
    const float* fc4b = (const float*)d_in[15];
    float* out = (float*)d_out;

    cudaFuncSetAttribute(fc_kernel, cudaFuncAttributeMaxDynamicSharedMemorySize,
                         FC_SMEM_BYTES);

    conv_kernel<<<M_TOT / 256, 256>>>(emb, edges, w1, b1, w2, b2, w3, b3);
    fc_kernel<<<M_TOT / MT, 256, FC_SMEM_BYTES>>>(fc1w, fc1b, fc2w, fc2b,
                                                  fc3w, fc3b, fc4w, fc4b);
    zero_rbc_kernel<<<1, 32>>>();
    prop_kernel<<<PPAIR / PW, PW * 32>>>(edges);
    norm_kernel<<<1, 32>>>(out);
}

// round 9
// speedup vs baseline: 4.5179x; 4.3395x over previous
#include <cuda_runtime.h>
#include <cstdint>

#define N_NODES 32
#define DIM 96
#define N_EDGES 256
#define PPAIR 1024
#define M_TOT (PPAIR * N_EDGES)   // 262144 samples

// ---------------- scratch (static device globals; no allocation) ----------------
__device__ float g_feat[M_TOT * 16];   // conv features (tf32-rounded fp32)
__device__ float g_preds[M_TOT];       // preds row-major: [p * 256 + e]
__device__ float g_rbc[N_NODES];
// weights pre-packed in m16n8k8 B-fragment order: [kt][nt][lane] -> float2 (b0,b1)
__device__ float2 g_w1f[2 * 16 * 32];    // K16  N128
__device__ float2 g_w2f[16 * 32 * 32];   // K128 N256
__device__ float2 g_w3f[32 * 16 * 32];   // K256 N128

// ---------------- helpers ----------------
__device__ __forceinline__ uint32_t f2tf32(float f) {
    uint32_t r;
    asm("cvt.rna.tf32.f32 %0, %1;" : "=r"(r) : "f"(f));
    return r;
}
__device__ __forceinline__ float tf32f(float f) {
    return __uint_as_float(f2tf32(f));
}
__device__ __forceinline__ void mma_tf32(float c[4], const uint32_t a[4],
                                         uint32_t b0, uint32_t b1) {
    asm("mma.sync.aligned.m16n8k8.row.col.f32.tf32.tf32.f32 "
        "{%0,%1,%2,%3}, {%4,%5,%6,%7}, {%8,%9}, {%0,%1,%2,%3};"
        : "+f"(c[0]), "+f"(c[1]), "+f"(c[2]), "+f"(c[3])
        : "r"(a[0]), "r"(a[1]), "r"(a[2]), "r"(a[3]), "r"(b0), "r"(b1));
}

// =======================================================================
// Kernel 0: pack weights into mma B-fragment order (tf32-rounded).
// b0 = W[k0][n], b1 = W[k0+4][n] with k0 = 8*kt + lane%4, n = 8*nt + lane/4.
// =======================================================================
__global__ void prep_weights(const float* __restrict__ fc1w,
                             const float* __restrict__ fc2w,
                             const float* __restrict__ fc3w)
{
    int i = blockIdx.x * 256 + threadIdx.x;   // 64 blocks -> i in [0, 16384)
    int ln = i & 31;
    {   // W2: KT=16, NT=32 (N=256)
        int nt = (i >> 5) & 31, kt = i >> 10;
        int k0 = 8 * kt + (ln & 3), n = 8 * nt + (ln >> 2);
        float2 v;
        v.x = tf32f(fc2w[k0 * 256 + n]);
        v.y = tf32f(fc2w[(k0 + 4) * 256 + n]);
        g_w2f[i] = v;
    }
    {   // W3: KT=32, NT=16 (N=128)
        int nt = (i >> 5) & 15, kt = i >> 9;
        int k0 = 8 * kt + (ln & 3), n = 8 * nt + (ln >> 2);
        float2 v;
        v.x = tf32f(fc3w[k0 * 128 + n]);
        v.y = tf32f(fc3w[(k0 + 4) * 128 + n]);
        g_w3f[i] = v;
    }
    if (i < 1024) {  // W1: KT=2, NT=16 (N=128)
        int nt = (i >> 5) & 15, kt = i >> 9;
        int k0 = 8 * kt + (ln & 3), n = 8 * nt + (ln >> 2);
        float2 v;
        v.x = tf32f(fc1w[k0 * 128 + n]);
        v.y = tf32f(fc1w[(k0 + 4) * 128 + n]);
        g_w1f[i] = v;
    }
}

// =======================================================================
// Kernel 1: conv stack. One thread per sample. semb padded to stride 97
// (97 % 32 == 1) so different-node lanes hit different banks.
// =======================================================================
#define EMB_STRIDE 97
__global__ void __launch_bounds__(256) conv_kernel(
    const float* __restrict__ emb, const int* __restrict__ edges,
    const float* __restrict__ w1, const float* __restrict__ b1,
    const float* __restrict__ w2, const float* __restrict__ b2,
    const float* __restrict__ w3, const float* __restrict__ b3)
{
    __shared__ float semb[N_NODES * EMB_STRIDE];
    __shared__ int   sedge[N_EDGES * 2];
    __shared__ float sw1[48], sb1[4], sw2[48], sb2[4], sw3[48], sb3[4];
    __shared__ float sfeat[256][17];

    int tid = threadIdx.x;
    for (int i = tid; i < N_NODES * DIM; i += 256)
        semb[(i / DIM) * EMB_STRIDE + (i % DIM)] = emb[i];
    for (int i = tid; i < N_EDGES * 2; i += 256) sedge[i] = edges[i];
    if (tid < 48) { sw1[tid] = w1[tid]; sw2[tid] = w2[tid]; sw3[tid] = w3[tid]; }
    if (tid < 4)  { sb1[tid] = b1[tid]; sb2[tid] = b2[tid]; sb3[tid] = b3[tid]; }
    __syncthreads();

    int gidx = blockIdx.x * 256 + tid;
    int p = gidx >> 8, e = gidx & 255;
    int s = p >> 5, t = p & 31;
    int xb[4];
    xb[0] = s * EMB_STRIDE;
    xb[1] = t * EMB_STRIDE;
    xb[2] = sedge[2 * e] * EMB_STRIDE;
    xb[3] = sedge[2 * e + 1] * EMB_STRIDE;

#pragma unroll
    for (int m = 0; m < 4; m++) {
        float h1c[4][10];
#pragma unroll
        for (int c = 0; c < 10; c++) {
            int pos0 = (4 * m + c) * 4;
            float xv[4][5];
#pragma unroll
            for (int i = 0; i < 4; i++)
#pragma unroll
                for (int pp = 0; pp < 5; pp++)
                    xv[i][pp] = semb[xb[i] + pos0 + pp];
#pragma unroll
            for (int o = 0; o < 4; o++) {
                float y0 = sb1[o], y1 = sb1[o];
#pragma unroll
                for (int i = 0; i < 4; i++)
#pragma unroll
                    for (int k = 0; k < 3; k++) {
                        float w = sw1[o * 12 + i * 3 + k];
                        y0 += w * xv[i][k];
                        y1 += w * xv[i][k + 2];
                    }
                h1c[o][c] = fmaxf(fmaxf(y0, y1), 0.f);
            }
        }
        float h2c[4][4];
#pragma unroll
        for (int c = 0; c < 4; c++) {
#pragma unroll
            for (int o = 0; o < 4; o++) {
                float y0 = sb2[o], y1 = sb2[o];
#pragma unroll
                for (int i = 0; i < 4; i++)
#pragma unroll
                    for (int k = 0; k < 3; k++) {
                        float w = sw2[o * 12 + i * 3 + k];
                        y0 += w * h1c[i][2 * c + k];
                        y1 += w * h1c[i][2 * c + 1 + k];
                    }
                h2c[o][c] = fmaxf(fmaxf(y0, y1), 0.f);
            }
        }
#pragma unroll
        for (int o = 0; o < 4; o++) {
            float y0 = sb3[o], y1 = sb3[o];
#pragma unroll
            for (int i = 0; i < 4; i++)
#pragma unroll
                for (int k = 0; k < 3; k++) {
                    float w = sw3[o * 12 + i * 3 + k];
                    y0 += w * h2c[i][k];
                    y1 += w * h2c[i][k + 1];
                }
            // tf32-round (RNE) so fc1 A-operands carry no truncation bias
            sfeat[tid][o * 4 + m] = tf32f(fmaxf(fmaxf(y0, y1), 0.f));
        }
    }
    __syncthreads();
#pragma unroll
    for (int ii = 0; ii < 16; ii++) {
        int l = tid + ii * 256;
        g_feat[blockIdx.x * 4096 + l] = sfeat[l >> 4][l & 15];
    }
}

// =======================================================================
// Kernel 2: fused FC stack on mma.sync tf32 (m16n8k8, baseline PTX — no
// sm_103a-only features). 256 rows/block, 8 warps x M32 (B-frag reuse
// across 2 m16 tiles). H1/H2 rows are warp-private -> __syncwarp only.
// A-operand smem strides 132/36 (== 4 mod 8) -> conflict-free frag loads.
// =======================================================================
#define SH1   0                    // [256][132] activations H1
#define SH1S  132
#define SH2   33792                // [256][36]  H2 chunk (N=32)
#define SH2S  36
#define SB2   43008                // 2048 float2: W2 chunk frags
#define SB3   47104                // 2048 float2: W3 chunk frags
#define SW1F  51200                // 1024 float2: W1 frags
#define SBIAS 53248                // b1(128) b2(256) b3(128) w4(128) b4(1)
#define FC_SMEM_FLOATS 54016
#define FC_SMEM_BYTES  (FC_SMEM_FLOATS * 4)

__global__ void __launch_bounds__(256, 1) fc_mma_kernel(
    const float* __restrict__ fc1b, const float* __restrict__ fc2b,
    const float* __restrict__ fc3b, const float* __restrict__ fc4w,
    const float* __restrict__ fc4b)
{
    extern __shared__ float sm[];
    int tid = threadIdx.x, wid = tid >> 5, lane = tid & 31;
    int r = lane >> 2, cc = lane & 3;
    int m0 = blockIdx.x * 256;
    int mb = wid * 32;

    // ---- stage W1 frags + biases ----
    float2* w1f = (float2*)(sm + SW1F);
    for (int i = tid; i < 1024; i += 256) w1f[i] = g_w1f[i];
    float* sb = sm + SBIAS;
    for (int i = tid; i < 641; i += 256) {
        float v;
        if (i < 128)      v = fc1b[i];
        else if (i < 384) v = fc2b[i - 128];
        else if (i < 512) v = fc3b[i - 384];
        else if (i < 640) v = fc4w[i - 512];
        else              v = fc4b[0];
        sb[i] = v;
    }
    __syncthreads();

    // ---- fc1: H1[256][128] = relu(F @ W1 + b1) ----
    {
        float C1[2][16][4];
#pragma unroll
        for (int mt = 0; mt < 2; mt++)
#pragma unroll
            for (int nt = 0; nt < 16; nt++)
#pragma unroll
                for (int q = 0; q < 4; q++) C1[mt][nt][q] = 0.f;

#pragma unroll
        for (int kt = 0; kt < 2; kt++) {
            uint32_t a[2][4];
#pragma unroll
            for (int mt = 0; mt < 2; mt++) {
                const float* fb = g_feat + (size_t)(m0 + mb + 16 * mt) * 16 + 8 * kt;
                a[mt][0] = __float_as_uint(fb[r * 16 + cc]);
                a[mt][1] = __float_as_uint(fb[(r + 8) * 16 + cc]);
                a[mt][2] = __float_as_uint(fb[r * 16 + cc + 4]);
                a[mt][3] = __float_as_uint(fb[(r + 8) * 16 + cc + 4]);
            }
#pragma unroll
            for (int nt = 0; nt < 16; nt++) {
                float2 bf = w1f[(kt * 16 + nt) * 32 + lane];
                uint32_t b0 = __float_as_uint(bf.x), b1 = __float_as_uint(bf.y);
                mma_tf32(C1[0][nt], a[0], b0, b1);
                mma_tf32(C1[1][nt], a[1], b0, b1);
            }
        }
#pragma unroll
        for (int mt = 0; mt < 2; mt++)
#pragma unroll
            for (int nt = 0; nt < 16; nt++) {
                int col = 8 * nt + 2 * cc;
                float bb0 = sb[col], bb1 = sb[col + 1];
                float* h  = sm + SH1 + (mb + 16 * mt + r) * SH1S;
                float* h8 = h + 8 * SH1S;
                h[col]      = tf32f(fmaxf(C1[mt][nt][0] + bb0, 0.f));
                h[col + 1]  = tf32f(fmaxf(C1[mt][nt][1] + bb1, 0.f));
                h8[col]     = tf32f(fmaxf(C1[mt][nt][2] + bb0, 0.f));
                h8[col + 1] = tf32f(fmaxf(C1[mt][nt][3] + bb1, 0.f));
            }
        __syncwarp();
    }

    // ---- fc2 + fc3, 8 chunks of N2=32 (fc3 accumulates over K=256) ----
    float C3[2][16][4];
#pragma unroll
    for (int mt = 0; mt < 2; mt++)
#pragma unroll
        for (int nt = 0; nt < 16; nt++)
#pragma unroll
            for (int q = 0; q < 4; q++) C3[mt][nt][q] = 0.f;

    float2* b2f = (float2*)(sm + SB2);
    float2* b3f = (float2*)(sm + SB3);

    for (int nc = 0; nc < 8; nc++) {
        __syncthreads();   // prior chunk's B reads complete
        for (int i = tid; i < 2048; i += 256) {
            int ln = i & 31, ntl = (i >> 5) & 3, kt = i >> 7;
            b2f[i] = g_w2f[(kt * 32 + nc * 4 + ntl) * 32 + ln];
        }
        for (int i = tid; i < 2048; i += 256) {
            int ln = i & 31, nt = (i >> 5) & 15, ktl = i >> 9;
            b3f[i] = g_w3f[((nc * 4 + ktl) * 16 + nt) * 32 + ln];
        }
        __syncthreads();

        // fc2: H2chunk[256][32] = relu(H1 @ W2[:, nc*32:+32] + b2)
        float C2[2][4][4];
#pragma unroll
        for (int mt = 0; mt < 2; mt++)
#pragma unroll
            for (int nt = 0; nt < 4; nt++)
#pragma unroll
                for (int q = 0; q < 4; q++) C2[mt][nt][q] = 0.f;

#pragma unroll 4
        for (int kt = 0; kt < 16; kt++) {
            uint32_t a[2][4];
#pragma unroll
            for (int mt = 0; mt < 2; mt++) {
                const float* h = sm + SH1 + (mb + 16 * mt) * SH1S + 8 * kt;
                a[mt][0] = __float_as_uint(h[r * SH1S + cc]);
                a[mt][1] = __float_as_uint(h[(r + 8) * SH1S + cc]);
                a[mt][2] = __float_as_uint(h[r * SH1S + cc + 4]);
                a[mt][3] = __float_as_uint(h[(r + 8) * SH1S + cc + 4]);
            }
#pragma unroll
            for (int ntl = 0; ntl < 4; ntl++) {
                float2 bf = b2f[(kt * 4 + ntl) * 32 + lane];
                uint32_t b0 = __float_as_uint(bf.x), b1 = __float_as_uint(bf.y);
                mma_tf32(C2[0][ntl], a[0], b0, b1);
                mma_tf32(C2[1][ntl], a[1], b0, b1);
            }
        }
#pragma unroll
        for (int mt = 0; mt < 2; mt++)
#pragma unroll
            for (int ntl = 0; ntl < 4; ntl++) {
                int col = 8 * ntl + 2 * cc;
                float bb0 = sb[128 + nc * 32 + col];
                float bb1 = sb[128 + nc * 32 + col + 1];
                float* h  = sm + SH2 + (mb + 16 * mt + r) * SH2S;
                float* h8 = h + 8 * SH2S;
                h[col]      = tf32f(fmaxf(C2[mt][ntl][0] + bb0, 0.f));
                h[col + 1]  = tf32f(fmaxf(C2[mt][ntl][1] + bb1, 0.f));
                h8[col]     = tf32f(fmaxf(C2[mt][ntl][2] + bb0, 0.f));
                h8[col + 1] = tf32f(fmaxf(C2[mt][ntl][3] + bb1, 0.f));
            }
        __syncwarp();

        // fc3: C3 += H2chunk @ W3[nc*32:+32, :]
#pragma unroll
        for (int ktl = 0; ktl < 4; ktl++) {
            uint32_t a[2][4];
#pragma unroll
            for (int mt = 0; mt < 2; mt++) {
                const float* h = sm + SH2 + (mb + 16 * mt) * SH2S + 8 * ktl;
                a[mt][0] = __float_as_uint(h[r * SH2S + cc]);
                a[mt][1] = __float_as_uint(h[(r + 8) * SH2S + cc]);
                a[mt][2] = __float_as_uint(h[r * SH2S + cc + 4]);
                a[mt][3] = __float_as_uint(h[(r + 8) * SH2S + cc + 4]);
            }
#pragma unroll
            for (int nt = 0; nt < 16; nt++) {
                float2 bf = b3f[(ktl * 16 + nt) * 32 + lane];
                uint32_t b0 = __float_as_uint(bf.x), b1 = __float_as_uint(bf.y);
                mma_tf32(C3[0][nt], a[0], b0, b1);
                mma_tf32(C3[1][nt], a[1], b0, b1);
            }
        }
    }

    // ---- fc4: pred = relu(C3 + b3) . w4 + b4; reduce over 4 cc-lanes ----
    float bias4 = sb[640];
#pragma unroll
    for (int mt = 0; mt < 2; mt++) {
        float acc0 = 0.f, acc1 = 0.f;
#pragma unroll
        for (int nt = 0; nt < 16; nt++) {
            int col = 8 * nt + 2 * cc;
            float b30 = sb[384 + col], b31 = sb[384 + col + 1];
            float w40 = sb[512 + col], w41 = sb[512 + col + 1];
            acc0 += fmaxf(C3[mt][nt][0] + b30, 0.f) * w40
                  + fmaxf(C3[mt][nt][1] + b31, 0.f) * w41;
            acc1 += fmaxf(C3[mt][nt][2] + b30, 0.f) * w40
                  + fmaxf(C3[mt][nt][3] + b31, 0.f) * w41;
        }
        acc0 += __shfl_xor_sync(0xffffffffu, acc0, 1);
        acc0 += __shfl_xor_sync(0xffffffffu, acc0, 2);
        acc1 += __shfl_xor_sync(0xffffffffu, acc1, 1);
        acc1 += __shfl_xor_sync(0xffffffffu, acc1, 2);
        if (cc == 0) {
            int g0 = m0 + mb + 16 * mt + r;
#pragma unroll
            for (int h = 0; h < 2; h++) {
                int gidx = g0 + h * 8;
                float pred = (h == 0 ? acc0 : acc1) + bias4;
                int p = gidx >> 8;
                if ((p >> 5) == (p & 31)) pred = 0.f;   // s == t mask
                g_preds[gidx] = pred;
            }
        }
    }
}

// =======================================================================
// Kernel 3: propagation — warp per row p (5.7us measured; unchanged).
// =======================================================================
#define PW 8
__global__ void __launch_bounds__(PW * 32) prop_kernel(const int* __restrict__ edges)
{
    __shared__ float spart[PW][32 * 33];
    __shared__ float srbc[N_NODES];
    __shared__ int sue[N_EDGES], sve[N_EDGES];

    int tid = threadIdx.x, l = tid & 31, w = tid >> 5;
    if (tid < 32) srbc[tid] = 0.f;
    for (int i = tid; i < N_EDGES; i += PW * 32) {
        sue[i] = edges[2 * i];
        sve[i] = edges[2 * i + 1];
    }
    __syncthreads();

    int p = blockIdx.x * PW + w;
    int s = p >> 5;

    int eu[8], ev[8];
    float pr[8];
#pragma unroll
    for (int k = 0; k < 8; k++) { eu[k] = sue[l * 8 + k]; ev[k] = sve[l * 8 + k]; }
    {
        float4 p0 = *(const float4*)&g_preds[p * 256 + l * 8];
        float4 p1 = *(const float4*)&g_preds[p * 256 + l * 8 + 4];
        pr[0] = p0.x; pr[1] = p0.y; pr[2] = p0.z; pr[3] = p0.w;
        pr[4] = p1.x; pr[5] = p1.y; pr[6] = p1.z; pr[7] = p1.w;
    }

    float x = (l == s) ? 1.f : 0.f;
    float racc = 0.f;
    float* part = spart[w];

    for (int step = 0; step < 3; step++) {
#pragma unroll
        for (int j = 0; j < 32; j++) part[l * 33 + j] = 0.f;
        __syncwarp();
#pragma unroll
        for (int k = 0; k < 8; k++) {
            float xv = __shfl_sync(0xffffffffu, x, eu[k]);
            part[l * 33 + ev[k]] += xv * pr[k];
        }
        __syncwarp();
        float xn = 0.f;
#pragma unroll
        for (int i = 0; i < 32; i++) xn += part[i * 33 + l];
        x = xn;
        racc += xn;
        __syncwarp();
    }

    atomicAdd(&srbc[l], racc);
    __syncthreads();
    if (tid < 32) atomicAdd(&g_rbc[tid], srbc[tid]);
}

__global__ void zero_rbc_kernel() {
    if (threadIdx.x < N_NODES) g_rbc[threadIdx.x] = 0.f;
}

__global__ void norm_kernel(float* __restrict__ out) {
    int l = threadIdx.x;
    float v = g_rbc[l];
    float sum = v;
#pragma unroll
    for (int o = 16; o > 0; o >>= 1) sum += __shfl_xor_sync(0xffffffffu, sum, o);
    out[l] = v / sum;
}

// =======================================================================
extern "C" void kernel_launch(void* const* d_in, const int* in_sizes, int n_in,
                              void* d_out, int out_size)
{
    const float* emb  = (const float*)d_in[0];
    const int*   edges= (const int*)  d_in[1];
    const float* w1   = (const float*)d_in[2];
    const float* b1   = (const float*)d_in[3];
    const float* w2   = (const float*)d_in[4];
    const float* b2   = (const float*)d_in[5];
    const float* w3   = (const float*)d_in[6];
    const float* b3   = (const float*)d_in[7];
    const float* fc1w = (const float*)d_in[8];
    const float* fc1b = (const float*)d_in[9];
    const float* fc2w = (const float*)d_in[10];
    const float* fc2b = (const float*)d_in[11];
    const float* fc3w = (const float*)d_in[12];
    const float* fc3b = (const float*)d_in[13];
    const float* fc4w = (const float*)d_in[14];
    const float* fc4b = (const float*)d_in[15];
    float* out = (float*)d_out;

    cudaFuncSetAttribute(fc_mma_kernel, cudaFuncAttributeMaxDynamicSharedMemorySize,
                         FC_SMEM_BYTES);

    prep_weights<<<64, 256>>>(fc1w, fc2w, fc3w);
    conv_kernel<<<M_TOT / 256, 256>>>(emb, edges, w1, b1, w2, b2, w3, b3);
    fc_mma_kernel<<<M_TOT / 256, 256, FC_SMEM_BYTES>>>(fc1b, fc2b, fc3b, fc4w, fc4b);
    zero_rbc_kernel<<<1, 32>>>();
    prop_kernel<<<PPAIR / PW, PW * 32>>>(edges);
    norm_kernel<<<1, 32>>>(out);
}

// round 10
// speedup vs baseline: 6.5213x; 1.4434x over previous
#include <cuda_runtime.h>
#include <cuda_fp16.h>
#include <cstdint>

#define N_NODES 32
#define DIM 96
#define N_EDGES 256
#define PPAIR 1024
#define M_TOT (PPAIR * N_EDGES)   // 262144 samples

// ---------------- scratch (static device globals; no allocation) ----------------
__device__ uint32_t g_feath[M_TOT * 8];  // conv features, half2 words [sample][8]
__device__ float g_preds[M_TOT];         // preds row-major: [p * 256 + e]
__device__ float g_rbc[N_NODES];
__device__ float g_tab[2 * 6016];        // conv1 tables: [role(u,v)][(o*47+pos)*32+node]
// weights pre-packed in m16n8k16 B-fragment half2 order
__device__ uint2 g_w1h[16 * 32];         // [nt][lane]        (K16  N128)
__device__ uint2 g_w2h[8 * 32 * 32];     // [kt][nt][lane]    (K128 N256)
__device__ uint2 g_w3h[16 * 16 * 32];    // [kt][nt][lane]    (K256 N128)

// ---------------- helpers ----------------
__device__ __forceinline__ uint32_t packh2(float a, float b) {
    __half2 h = __floats2half2_rn(a, b);
    return *(uint32_t*)&h;
}
__device__ __forceinline__ void mma_f16(float c[4], const uint32_t a[4],
                                        uint32_t b0, uint32_t b1) {
    asm("mma.sync.aligned.m16n8k16.row.col.f32.f16.f16.f32 "
        "{%0,%1,%2,%3}, {%4,%5,%6,%7}, {%8,%9}, {%0,%1,%2,%3};"
        : "+f"(c[0]), "+f"(c[1]), "+f"(c[2]), "+f"(c[3])
        : "r"(a[0]), "r"(a[1]), "r"(a[2]), "r"(a[3]), "r"(b0), "r"(b1));
}

// =======================================================================
// Kernel 0a: pack FC weights into m16n8k16 B-fragment half2 order.
// b0 = {W[k0][n], W[k0+1][n]}, b1 = {W[k0+8][n], W[k0+9][n]},
// k0 = kt*16 + (lane%4)*2, n = nt*8 + lane/4.
// =======================================================================
__global__ void prep_weights(const float* __restrict__ fc1w,
                             const float* __restrict__ fc2w,
                             const float* __restrict__ fc3w)
{
    int i = blockIdx.x * 256 + threadIdx.x;   // 66 blocks -> [0, 16896)
    int ln = i & 31;
    if (i < 8192) {   // W2: KT=8 (K128), NT=32 (N256)
        int nt = (i >> 5) & 31, kt = i >> 10;
        int k0 = 16 * kt + (ln & 3) * 2, n = 8 * nt + (ln >> 2);
        uint2 v;
        v.x = packh2(fc2w[k0 * 256 + n], fc2w[(k0 + 1) * 256 + n]);
        v.y = packh2(fc2w[(k0 + 8) * 256 + n], fc2w[(k0 + 9) * 256 + n]);
        g_w2h[i] = v;
    }
    if (i < 8192) {   // W3: KT=16 (K256), NT=16 (N128)
        int nt = (i >> 5) & 15, kt = i >> 9;
        int k0 = 16 * kt + (ln & 3) * 2, n = 8 * nt + (ln >> 2);
        uint2 v;
        v.x = packh2(fc3w[k0 * 128 + n], fc3w[(k0 + 1) * 128 + n]);
        v.y = packh2(fc3w[(k0 + 8) * 128 + n], fc3w[(k0 + 9) * 128 + n]);
        g_w3h[i] = v;
    }
    if (i < 512) {    // W1: KT=1 (K16), NT=16 (N128)
        int nt = i >> 5;
        int k0 = (ln & 3) * 2, n = 8 * nt + (ln >> 2);
        uint2 v;
        v.x = packh2(fc1w[k0 * 128 + n], fc1w[(k0 + 1) * 128 + n]);
        v.y = packh2(fc1w[(k0 + 8) * 128 + n], fc1w[(k0 + 9) * 128 + n]);
        g_w1h[i] = v;
    }
}

// =======================================================================
// Kernel 0b: conv1 channel tables for roles u (ch2) and v (ch3):
// g_tab[role*6016 + (o*47+pos)*32 + node] = sum_k w1[o][ch][k]*emb[node][2*pos+k]
// =======================================================================
__global__ void prep_tab(const float* __restrict__ emb, const float* __restrict__ w1)
{
    int i = blockIdx.x * 256 + threadIdx.x;   // 47 blocks -> [0, 12032)
    if (i >= 12032) return;
    int role = (i >= 6016) ? 1 : 0;
    int rem = i - role * 6016;
    int o = rem / 1504;
    int pos = (rem >> 5) % 47;
    int node = rem & 31;
    int ch = 2 + role;
    float acc = 0.f;
#pragma unroll
    for (int k = 0; k < 3; k++)
        acc += w1[o * 12 + ch * 3 + k] * emb[node * DIM + 2 * pos + k];
    g_tab[i] = acc;
}

// =======================================================================
// Kernel 1: conv stack. Block = one p (s,t fixed), 256 threads = 256 e.
// conv1 via precomputed tables: y1[o][q] = sum_st[o][q] + tabu[u] + tabv[v].
// Table layout node-fastest -> warp gather is conflict-free/broadcast.
// =======================================================================
__global__ void __launch_bounds__(256) conv_kernel(
    const float* __restrict__ emb, const int* __restrict__ edges,
    const float* __restrict__ w1, const float* __restrict__ b1,
    const float* __restrict__ w2, const float* __restrict__ b2,
    const float* __restrict__ w3, const float* __restrict__ b3)
{
    __shared__ float stab[2 * 6016];     // 48KB: u tables then v tables
    __shared__ float ssum[188];          // sum_st[o*47+pos] (incl. b1)
    __shared__ int   sedge[N_EDGES * 2];
    __shared__ float sw2[48], sb2_[4], sw3[48], sb3_[4];
    __shared__ float sfeat[256][17];

    int tid = threadIdx.x;
    int p = blockIdx.x;
    int s = p >> 5, t = p & 31;

    for (int i = tid; i < 12032; i += 256) stab[i] = g_tab[i];
    for (int i = tid; i < N_EDGES * 2; i += 256) sedge[i] = edges[i];
    if (tid < 48) { sw2[tid] = w2[tid]; sw3[tid] = w3[tid]; }
    if (tid < 4)  { sb2_[tid] = b2[tid]; sb3_[tid] = b3[tid]; }
    if (tid < 188) {
        int o = tid / 47, pos = tid % 47;
        float acc = b1[o];
#pragma unroll
        for (int k = 0; k < 3; k++) {
            acc += w1[o * 12 + 0 * 3 + k] * emb[s * DIM + 2 * pos + k];
            acc += w1[o * 12 + 1 * 3 + k] * emb[t * DIM + 2 * pos + k];
        }
        ssum[tid] = acc;
    }
    __syncthreads();

    int e = tid;
    int uoff = sedge[2 * e];            // role-u table base (+node)
    int voff = 6016 + sedge[2 * e + 1]; // role-v table base (+node)

#pragma unroll
    for (int m = 0; m < 4; m++) {
        float h1c[4][10];
#pragma unroll
        for (int c = 0; c < 10; c++) {
            int j = 4 * m + c;
            int q0 = 2 * j, q1 = 2 * j + 1;
#pragma unroll
            for (int o = 0; o < 4; o++) {
                int i0 = o * 47 + q0, i1 = o * 47 + q1;
                float v0 = ssum[i0] + stab[uoff + i0 * 32] + stab[voff + i0 * 32];
                float v1 = ssum[i1] + stab[uoff + i1 * 32] + stab[voff + i1 * 32];
                h1c[o][c] = fmaxf(fmaxf(v0, v1), 0.f);
            }
        }
        float h2c[4][4];
#pragma unroll
        for (int c = 0; c < 4; c++) {
#pragma unroll
            for (int o = 0; o < 4; o++) {
                float y0 = sb2_[o], y1 = sb2_[o];
#pragma unroll
                for (int i = 0; i < 4; i++)
#pragma unroll
                    for (int k = 0; k < 3; k++) {
                        float w = sw2[o * 12 + i * 3 + k];
                        y0 += w * h1c[i][2 * c + k];
                        y1 += w * h1c[i][2 * c + 1 + k];
                    }
                h2c[o][c] = fmaxf(fmaxf(y0, y1), 0.f);
            }
        }
#pragma unroll
        for (int o = 0; o < 4; o++) {
            float y0 = sb3_[o], y1 = sb3_[o];
#pragma unroll
            for (int i = 0; i < 4; i++)
#pragma unroll
                for (int k = 0; k < 3; k++) {
                    float w = sw3[o * 12 + i * 3 + k];
                    y0 += w * h2c[i][k];
                    y1 += w * h2c[i][k + 1];
                }
            sfeat[tid][o * 4 + m] = fmaxf(fmaxf(y0, y1), 0.f);
        }
    }
    __syncthreads();
    // pack features to half2 words, coalesced: g_feath[gidx*8 + wc]
#pragma unroll
    for (int ii = 0; ii < 8; ii++) {
        int idx = tid + ii * 256;        // 0..2047
        int l2 = idx >> 3, wc = idx & 7;
        g_feath[blockIdx.x * 2048 + idx] =
            packh2(sfeat[l2][2 * wc], sfeat[l2][2 * wc + 1]);
    }
}

// =======================================================================
// Kernel 2: fused FC stack on mma.sync fp16 m16n8k16 (fp32 accum).
// 256 rows/block, 8 warps x M32. Activations half2 in smem; word strides
// 68 / 20 (== 4 mod 8) -> conflict-free A-fragment loads.
// =======================================================================
#define SH1   0                    // [256][68 words] H1 half2
#define SH1S  68
#define SH2   17408                // [256][20 words] H2 chunk half2
#define SH2S  20
#define SB2   22528                // 1024 uint2 W2 chunk frags
#define SB3   24576                // 1024 uint2 W3 chunk frags
#define SW1F  26624                // 512 uint2 W1 frags
#define SBIAS 27648                // f32: b1(128) b2(256) b3(128) w4(128) b4(1)
#define FC_SMEM_WORDS 28289
#define FC_SMEM_BYTES (FC_SMEM_WORDS * 4)

__global__ void __launch_bounds__(256, 1) fc_mma_kernel(
    const float* __restrict__ fc1b, const float* __restrict__ fc2b,
    const float* __restrict__ fc3b, const float* __restrict__ fc4w,
    const float* __restrict__ fc4b)
{
    extern __shared__ uint32_t smw[];
    uint32_t* sH1w = smw + SH1;
    uint32_t* sH2w = smw + SH2;
    uint2* b2f = (uint2*)(smw + SB2);
    uint2* b3f = (uint2*)(smw + SB3);
    uint2* w1f = (uint2*)(smw + SW1F);
    float* sb  = (float*)(smw + SBIAS);

    int tid = threadIdx.x, wid = tid >> 5, lane = tid & 31;
    int r = lane >> 2, cc = lane & 3;
    int m0 = blockIdx.x * 256;
    int mb = wid * 32;

    for (int i = tid; i < 512; i += 256) w1f[i] = g_w1h[i];
    for (int i = tid; i < 641; i += 256) {
        float v;
        if (i < 128)      v = fc1b[i];
        else if (i < 384) v = fc2b[i - 128];
        else if (i < 512) v = fc3b[i - 384];
        else if (i < 640) v = fc4w[i - 512];
        else              v = fc4b[0];
        sb[i] = v;
    }
    __syncthreads();

    // ---- fc1: H1[256][128] = relu(F @ W1 + b1)  (K=16, 1 k-step) ----
    {
        float C1[2][16][4];
#pragma unroll
        for (int mt = 0; mt < 2; mt++)
#pragma unroll
            for (int nt = 0; nt < 16; nt++)
#pragma unroll
                for (int q = 0; q < 4; q++) C1[mt][nt][q] = 0.f;

        uint32_t a[2][4];
#pragma unroll
        for (int mt = 0; mt < 2; mt++) {
            int base = (m0 + mb + 16 * mt) * 8;
            a[mt][0] = g_feath[base + r * 8 + cc];
            a[mt][1] = g_feath[base + (r + 8) * 8 + cc];
            a[mt][2] = g_feath[base + r * 8 + cc + 4];
            a[mt][3] = g_feath[base + (r + 8) * 8 + cc + 4];
        }
#pragma unroll
        for (int nt = 0; nt < 16; nt++) {
            uint2 bf = w1f[nt * 32 + lane];
            mma_f16(C1[0][nt], a[0], bf.x, bf.y);
            mma_f16(C1[1][nt], a[1], bf.x, bf.y);
        }
#pragma unroll
        for (int mt = 0; mt < 2; mt++)
#pragma unroll
            for (int nt = 0; nt < 16; nt++) {
                int col = 8 * nt + 2 * cc;
                float b0 = sb[col], b1 = sb[col + 1];
                int row = mb + 16 * mt + r;
                sH1w[row * SH1S + 4 * nt + cc] =
                    packh2(fmaxf(C1[mt][nt][0] + b0, 0.f),
                           fmaxf(C1[mt][nt][1] + b1, 0.f));
                sH1w[(row + 8) * SH1S + 4 * nt + cc] =
                    packh2(fmaxf(C1[mt][nt][2] + b0, 0.f),
                           fmaxf(C1[mt][nt][3] + b1, 0.f));
            }
        __syncwarp();
    }

    // ---- fc2 + fc3, 8 chunks of N2=32 (fc3 accumulates over K=256) ----
    float C3[2][16][4];
#pragma unroll
    for (int mt = 0; mt < 2; mt++)
#pragma unroll
        for (int nt = 0; nt < 16; nt++)
#pragma unroll
            for (int q = 0; q < 4; q++) C3[mt][nt][q] = 0.f;

    for (int nc = 0; nc < 8; nc++) {
        __syncthreads();   // prior chunk's B reads complete
        for (int i = tid; i < 1024; i += 256) {
            int ln = i & 31, ntl = (i >> 5) & 3, kt = i >> 7;
            b2f[i] = g_w2h[(kt * 32 + nc * 4 + ntl) * 32 + ln];
        }
        for (int i = tid; i < 1024; i += 256) {
            int ln = i & 31, nt = (i >> 5) & 15, ktl = i >> 9;
            b3f[i] = g_w3h[((nc * 2 + ktl) * 16 + nt) * 32 + ln];
        }
        __syncthreads();

        // fc2: H2chunk[256][32] = relu(H1 @ W2[:, nc*32:+32] + b2)
        float C2[2][4][4];
#pragma unroll
        for (int mt = 0; mt < 2; mt++)
#pragma unroll
            for (int nt = 0; nt < 4; nt++)
#pragma unroll
                for (int q = 0; q < 4; q++) C2[mt][nt][q] = 0.f;

#pragma unroll
        for (int kt = 0; kt < 8; kt++) {
            uint32_t a[2][4];
#pragma unroll
            for (int mt = 0; mt < 2; mt++) {
                int rb = (mb + 16 * mt) * SH1S + kt * 8;
                a[mt][0] = sH1w[rb + r * SH1S + cc];
                a[mt][1] = sH1w[rb + (r + 8) * SH1S + cc];
                a[mt][2] = sH1w[rb + r * SH1S + cc + 4];
                a[mt][3] = sH1w[rb + (r + 8) * SH1S + cc + 4];
            }
#pragma unroll
            for (int ntl = 0; ntl < 4; ntl++) {
                uint2 bf = b2f[(kt * 4 + ntl) * 32 + lane];
                mma_f16(C2[0][ntl], a[0], bf.x, bf.y);
                mma_f16(C2[1][ntl], a[1], bf.x, bf.y);
            }
        }
#pragma unroll
        for (int mt = 0; mt < 2; mt++)
#pragma unroll
            for (int ntl = 0; ntl < 4; ntl++) {
                int col = 8 * ntl + 2 * cc;
                float b0 = sb[128 + nc * 32 + col];
                float b1 = sb[128 + nc * 32 + col + 1];
                int row = mb + 16 * mt + r;
                sH2w[row * SH2S + 4 * ntl + cc] =
                    packh2(fmaxf(C2[mt][ntl][0] + b0, 0.f),
                           fmaxf(C2[mt][ntl][1] + b1, 0.f));
                sH2w[(row + 8) * SH2S + 4 * ntl + cc] =
                    packh2(fmaxf(C2[mt][ntl][2] + b0, 0.f),
                           fmaxf(C2[mt][ntl][3] + b1, 0.f));
            }
        __syncwarp();

        // fc3: C3 += H2chunk @ W3[nc*32:+32, :]
#pragma unroll
        for (int ktl = 0; ktl < 2; ktl++) {
            uint32_t a[2][4];
#pragma unroll
            for (int mt = 0; mt < 2; mt++) {
                int rb = (mb + 16 * mt) * SH2S + ktl * 8;
                a[mt][0] = sH2w[rb + r * SH2S + cc];
                a[mt][1] = sH2w[rb + (r + 8) * SH2S + cc];
                a[mt][2] = sH2w[rb + r * SH2S + cc + 4];
                a[mt][3] = sH2w[rb + (r + 8) * SH2S + cc + 4];
            }
#pragma unroll
            for (int nt = 0; nt < 16; nt++) {
                uint2 bf = b3f[(ktl * 16 + nt) * 32 + lane];
                mma_f16(C3[0][nt], a[0], bf.x, bf.y);
                mma_f16(C3[1][nt], a[1], bf.x, bf.y);
            }
        }
    }

    // ---- fc4: pred = relu(C3 + b3) . w4 + b4; reduce over 4 cc-lanes ----
    float bias4 = sb[640];
#pragma unroll
    for (int mt = 0; mt < 2; mt++) {
        float acc0 = 0.f, acc1 = 0.f;
#pragma unroll
        for (int nt = 0; nt < 16; nt++) {
            int col = 8 * nt + 2 * cc;
            float b30 = sb[384 + col], b31 = sb[384 + col + 1];
            float w40 = sb[512 + col], w41 = sb[512 + col + 1];
            acc0 += fmaxf(C3[mt][nt][0] + b30, 0.f) * w40
                  + fmaxf(C3[mt][nt][1] + b31, 0.f) * w41;
            acc1 += fmaxf(C3[mt][nt][2] + b30, 0.f) * w40
                  + fmaxf(C3[mt][nt][3] + b31, 0.f) * w41;
        }
        acc0 += __shfl_xor_sync(0xffffffffu, acc0, 1);
        acc0 += __shfl_xor_sync(0xffffffffu, acc0, 2);
        acc1 += __shfl_xor_sync(0xffffffffu, acc1, 1);
        acc1 += __shfl_xor_sync(0xffffffffu, acc1, 2);
        if (cc == 0) {
            int g0 = m0 + mb + 16 * mt + r;
#pragma unroll
            for (int h = 0; h < 2; h++) {
                int gidx = g0 + h * 8;
                float pred = (h == 0 ? acc0 : acc1) + bias4;
                int p = gidx >> 8;
                if ((p >> 5) == (p & 31)) pred = 0.f;   // s == t mask
                g_preds[gidx] = pred;
            }
        }
    }
}

// =======================================================================
// Kernel 3: propagation — warp per row p (5.7us measured; unchanged).
// =======================================================================
#define PW 8
__global__ void __launch_bounds__(PW * 32) prop_kernel(const int* __restrict__ edges)
{
    __shared__ float spart[PW][32 * 33];
    __shared__ float srbc[N_NODES];
    __shared__ int sue[N_EDGES], sve[N_EDGES];

    int tid = threadIdx.x, l = tid & 31, w = tid >> 5;
    if (tid < 32) srbc[tid] = 0.f;
    for (int i = tid; i < N_EDGES; i += PW * 32) {
        sue[i] = edges[2 * i];
        sve[i] = edges[2 * i + 1];
    }
    __syncthreads();

    int p = blockIdx.x * PW + w;
    int s = p >> 5;

    int eu[8], ev[8];
    float pr[8];
#pragma unroll
    for (int k = 0; k < 8; k++) { eu[k] = sue[l * 8 + k]; ev[k] = sve[l * 8 + k]; }
    {
        float4 p0 = *(const float4*)&g_preds[p * 256 + l * 8];
        float4 p1 = *(const float4*)&g_preds[p * 256 + l * 8 + 4];
        pr[0] = p0.x; pr[1] = p0.y; pr[2] = p0.z; pr[3] = p0.w;
        pr[4] = p1.x; pr[5] = p1.y; pr[6] = p1.z; pr[7] = p1.w;
    }

    float x = (l == s) ? 1.f : 0.f;
    float racc = 0.f;
    float* part = spart[w];

    for (int step = 0; step < 3; step++) {
#pragma unroll
        for (int j = 0; j < 32; j++) part[l * 33 + j] = 0.f;
        __syncwarp();
#pragma unroll
        for (int k = 0; k < 8; k++) {
            float xv = __shfl_sync(0xffffffffu, x, eu[k]);
            part[l * 33 + ev[k]] += xv * pr[k];
        }
        __syncwarp();
        float xn = 0.f;
#pragma unroll
        for (int i = 0; i < 32; i++) xn += part[i * 33 + l];
        x = xn;
        racc += xn;
        __syncwarp();
    }

    atomicAdd(&srbc[l], racc);
    __syncthreads();
    if (tid < 32) atomicAdd(&g_rbc[tid], srbc[tid]);
}

__global__ void zero_rbc_kernel() {
    if (threadIdx.x < N_NODES) g_rbc[threadIdx.x] = 0.f;
}

__global__ void norm_kernel(float* __restrict__ out) {
    int l = threadIdx.x;
    float v = g_rbc[l];
    float sum = v;
#pragma unroll
    for (int o = 16; o > 0; o >>= 1) sum += __shfl_xor_sync(0xffffffffu, sum, o);
    out[l] = v / sum;
}

// =======================================================================
extern "C" void kernel_launch(void* const* d_in, const int* in_sizes, int n_in,
                              void* d_out, int out_size)
{
    const float* emb  = (const float*)d_in[0];
    const int*   edges= (const int*)  d_in[1];
    const float* w1   = (const float*)d_in[2];
    const float* b1   = (const float*)d_in[3];
    const float* w2   = (const float*)d_in[4];
    const float* b2   = (const float*)d_in[5];
    const float* w3   = (const float*)d_in[6];
    const float* b3   = (const float*)d_in[7];
    const float* fc1w = (const float*)d_in[8];
    const float* fc1b = (const float*)d_in[9];
    const float* fc2w = (const float*)d_in[10];
    const float* fc2b = (const float*)d_in[11];
    const float* fc3w = (const float*)d_in[12];
    const float* fc3b = (const float*)d_in[13];
    const float* fc4w = (const float*)d_in[14];
    const float* fc4b = (const float*)d_in[15];
    float* out = (float*)d_out;

    cudaFuncSetAttribute(fc_mma_kernel, cudaFuncAttributeMaxDynamicSharedMemorySize,
                         FC_SMEM_BYTES);

    prep_weights<<<66, 256>>>(fc1w, fc2w, fc3w);
    prep_tab<<<47, 256>>>(emb, w1);
    conv_kernel<<<PPAIR, 256>>>(emb, edges, w1, b1, w2, b2, w3, b3);
    fc_mma_kernel<<<M_TOT / 256, 256, FC_SMEM_BYTES>>>(fc1b, fc2b, fc3b, fc4w, fc4b);
    zero_rbc_kernel<<<1, 32>>>();
    prop_kernel<<<PPAIR / PW, PW * 32>>>(edges);
    norm_kernel<<<1, 32>>>(out);
}